// round 5
// baseline (speedup 1.0000x reference)
#include <cuda_runtime.h>
#include <cuda_bf16.h>

// Problem: softmask [B=16, K=64, H=240, W=320] fp32.
// out = sqrt( sum over 1024 slices of unbiased variance over H*W=76800 elems )
//
// Streaming has been bandwidth-invariant (~6.25-6.28 TB/s) across grid
// shapes / occupancy / cache hints -> at the chip's streaming ceiling.
// This round: Blackwell 256-bit loads (ld.global.nc.v8.f32, LDG.E.256)
// to halve LDG count and per-byte L1tex wavefront overhead.
// Tail: fixed-point u64 atomicAdd (bit-deterministic, order-independent),
// last CTA finalizes + resets (graph-replay safe).

#define HW        76800            // 240*320
#define HW8       (HW / 8)         // 9600 v8-loads per slice
#define NSLICES   1024             // 16*64
#define NTHREADS  256
#define FP_SCALE  1099511627776.0  // 2^40

__device__ unsigned long long g_acc   = 0ull;
__device__ unsigned int       g_count = 0;

__global__ __launch_bounds__(NTHREADS)
void loss_concentration_fused(const float* __restrict__ in,
                              float* __restrict__ out) {
    const int s = blockIdx.x;
    const float* __restrict__ p = in + (size_t)s * HW;   // 32B-aligned base

    float sum = 0.f, sq = 0.f;

    // 9600 / 256 = 37.5 iterations per thread, 32 bytes per load.
    #pragma unroll 5
    for (int i = threadIdx.x; i < HW8; i += NTHREADS) {
        float a0, a1, a2, a3, a4, a5, a6, a7;
        const float* q = p + (size_t)i * 8;
        asm volatile(
            "ld.global.nc.v8.f32 {%0,%1,%2,%3,%4,%5,%6,%7}, [%8];"
            : "=f"(a0), "=f"(a1), "=f"(a2), "=f"(a3),
              "=f"(a4), "=f"(a5), "=f"(a6), "=f"(a7)
            : "l"(q));
        sum += ((a0 + a1) + (a2 + a3)) + ((a4 + a5) + (a6 + a7));
        sq  += ((a0 * a0 + a1 * a1) + (a2 * a2 + a3 * a3))
             + ((a4 * a4 + a5 * a5) + (a6 * a6 + a7 * a7));
    }

    // warp reduce
    #pragma unroll
    for (int off = 16; off > 0; off >>= 1) {
        sum += __shfl_xor_sync(0xffffffffu, sum, off);
        sq  += __shfl_xor_sync(0xffffffffu, sq,  off);
    }

    __shared__ float s_sum[NTHREADS / 32];
    __shared__ float s_sq [NTHREADS / 32];
    const int lane = threadIdx.x & 31;
    const int wid  = threadIdx.x >> 5;
    if (lane == 0) { s_sum[wid] = sum; s_sq[wid] = sq; }
    __syncthreads();

    if (threadIdx.x == 0) {
        float tsum = 0.f, tsq = 0.f;
        #pragma unroll
        for (int w = 0; w < NTHREADS / 32; w++) { tsum += s_sum[w]; tsq += s_sq[w]; }
        // unbiased: (sumsq - sum^2/n) / (n-1)
        float var = (tsq - tsum * tsum * (1.0f / (float)HW))
                    * (1.0f / (float)(HW - 1));
        if (var < 0.f) var = 0.f;                // numerical guard
        // fixed-point contribution: deterministic under any atomic order
        unsigned long long q =
            (unsigned long long)(__double2ll_rn((double)var * FP_SCALE));
        atomicAdd(&g_acc, q);
        __threadfence();                         // acc visible before count
        unsigned old = atomicAdd(&g_count, 1u);
        if (old == NSLICES - 1) {
            unsigned long long total = atomicAdd(&g_acc, 0ull);  // coherent read
            out[0] = sqrtf((float)((double)total * (1.0 / FP_SCALE)));
            g_acc   = 0ull;                      // reset for next graph replay
            g_count = 0;
        }
    }
}

extern "C" void kernel_launch(void* const* d_in, const int* in_sizes, int n_in,
                              void* d_out, int out_size) {
    const float* in = (const float*)d_in[0];
    float* out = (float*)d_out;
    loss_concentration_fused<<<NSLICES, NTHREADS>>>(in, out);
}

// round 7
// speedup vs baseline: 1.0144x; 1.0144x over previous
#include <cuda_runtime.h>
#include <cuda_bf16.h>

// Problem: softmask [B=16, K=64, H=240, W=320] fp32.
// out = sqrt( sum over 1024 slices of unbiased variance over H*W=76800 elems )
//
// ROOFLINE-FROZEN configuration (R4, best measured 51.26us):
// DRAM throughput is pinned at 6.16-6.28 TB/s across every tested variation
// (grid shape, occupancy, cache hints, 128b/256b loads) -> machine streaming
// ceiling. 314.6 MB / 6278 GB/s = 50.1us pure transfer; kernel = 50.7us.
//   - one CTA per slice, float4 streaming loads with evict-first hint
//   - two independent accumulator pairs to shorten FFMA chains (free)
//   - cross-slice sum via fixed-point u64 atomicAdd (bit-deterministic,
//     arrival-order independent), overlapped with other CTAs' streaming
//   - last CTA finalizes sqrt + resets counters (graph-replay safe)

#define HW        76800            // 240*320
#define HW4       (HW / 4)         // 19200 float4 per slice
#define NSLICES   1024             // 16*64
#define NTHREADS  256
#define FP_SCALE  1099511627776.0  // 2^40

__device__ unsigned long long g_acc   = 0ull;
__device__ unsigned int       g_count = 0;

__global__ __launch_bounds__(NTHREADS)
void loss_concentration_fused(const float4* __restrict__ in,
                              float* __restrict__ out) {
    const int s = blockIdx.x;
    const float4* __restrict__ p = in + (size_t)s * HW4;

    float sum0 = 0.f, sq0 = 0.f;     // two independent chains
    float sum1 = 0.f, sq1 = 0.f;

    // 19200 / 256 = 75 iterations per thread; streaming (evict-first) loads.
    #pragma unroll 5
    for (int i = threadIdx.x; i < HW4; i += NTHREADS) {
        float4 v = __ldcs(&p[i]);
        sum0 += v.x + v.y;
        sum1 += v.z + v.w;
        sq0  += v.x * v.x + v.y * v.y;
        sq1  += v.z * v.z + v.w * v.w;
    }
    float sum = sum0 + sum1;
    float sq  = sq0  + sq1;

    // warp reduce
    #pragma unroll
    for (int off = 16; off > 0; off >>= 1) {
        sum += __shfl_xor_sync(0xffffffffu, sum, off);
        sq  += __shfl_xor_sync(0xffffffffu, sq,  off);
    }

    __shared__ float s_sum[NTHREADS / 32];
    __shared__ float s_sq [NTHREADS / 32];
    const int lane = threadIdx.x & 31;
    const int wid  = threadIdx.x >> 5;
    if (lane == 0) { s_sum[wid] = sum; s_sq[wid] = sq; }
    __syncthreads();

    if (threadIdx.x == 0) {
        float tsum = 0.f, tsq = 0.f;
        #pragma unroll
        for (int w = 0; w < NTHREADS / 32; w++) { tsum += s_sum[w]; tsq += s_sq[w]; }
        // unbiased: (sumsq - sum^2/n) / (n-1)
        float var = (tsq - tsum * tsum * (1.0f / (float)HW))
                    * (1.0f / (float)(HW - 1));
        if (var < 0.f) var = 0.f;                // numerical guard
        // fixed-point contribution: deterministic under any atomic order
        unsigned long long q =
            (unsigned long long)(__double2ll_rn((double)var * FP_SCALE));
        atomicAdd(&g_acc, q);
        __threadfence();                         // acc visible before count
        unsigned old = atomicAdd(&g_count, 1u);
        if (old == NSLICES - 1) {
            unsigned long long total = atomicAdd(&g_acc, 0ull);  // coherent read
            out[0] = sqrtf((float)((double)total * (1.0 / FP_SCALE)));
            g_acc   = 0ull;                      // reset for next graph replay
            g_count = 0;
        }
    }
}

extern "C" void kernel_launch(void* const* d_in, const int* in_sizes, int n_in,
                              void* d_out, int out_size) {
    const float4* in = (const float4*)d_in[0];
    float* out = (float*)d_out;
    loss_concentration_fused<<<NSLICES, NTHREADS>>>(in, out);
}